// round 16
// baseline (speedup 1.0000x reference)
#include <cuda_runtime.h>
#include <cuda_bf16.h>
#include <math.h>
#include <stdint.h>

#define M_LIB   200000
#define M_PAD   203648          // 37 * 5504, zero-padded tail (bss)
#define N_PATCH 676
#define NPAD    768
#define DIM     384
#define IMG     224
#define SIGMA   4.0f
#define KRAD    16

#define NTILES  43              // 128-row tiles per stripe; 37 stripes
#define STRIPE  (128*NTILES)    // 5504
#define NITER   (NTILES*3)      // 129 k-third stages (128 int8 each)
#define STG_BYTES (128*128)     // one stage: 128 rows x 128 int8 (128B pitch)
#define SM_P    0               // patch chunk 96 x 384B = 36864
#define SM_L    36864
#define SM_MIN  (SM_L + 2*STG_BYTES)   // 69632
#define SMEM_MAIN (SM_MIN + 96*8)      // 70400

// ---------------- device scratch ----------------
__device__ __align__(16) signed char g_lib_i8[(size_t)M_PAD * DIM];   // pad rows stay 0
__device__ float g_lscale[M_PAD];                                      // pad -> 0
__device__ __align__(16) signed char g_patch_i8[NPAD * DIM];
__device__ float g_patch_n[N_PATCH * DIM];
__device__ float g_pn[N_PATCH];
__device__ unsigned long long g_minbuf[NPAD];
__device__ float g_minval[N_PATCH];
__device__ int   g_sidx;
__device__ int   g_mstar_idx;
__device__ float g_sstar;
__device__ float g_d2star[M_LIB];
__device__ unsigned long long g_btop[64 * 5];
__device__ int   g_nn[5];

// ---------------- helpers ----------------
__device__ __forceinline__ unsigned fordu(float f) {
    unsigned u = __float_as_uint(f);
    return (u & 0x80000000u) ? ~u : (u | 0x80000000u);
}
__device__ __forceinline__ float fordu_inv(unsigned e) {
    return __uint_as_float((e & 0x80000000u) ? (e ^ 0x80000000u) : ~e);
}
__device__ __forceinline__ unsigned long long packkey(float v, int idx) {
    return ((unsigned long long)fordu(v) << 32) | (unsigned)idx;
}
__device__ __forceinline__ unsigned long long ullmin2(unsigned long long a, unsigned long long b) {
    return a < b ? a : b;
}
#define INF_F (__int_as_float(0x7f800000))

__device__ __forceinline__ uint32_t smem_u32(const void* p) {
    return (uint32_t)__cvta_generic_to_shared(p);
}

#define LDSM4(r0,r1,r2,r3,addr) \
    asm volatile("ldmatrix.sync.aligned.m8n8.x4.shared.b16 {%0,%1,%2,%3}, [%4];" \
        : "=r"(r0), "=r"(r1), "=r"(r2), "=r"(r3) : "r"(addr))
// int8 IMMA: m16n8k32, s8 x s8 -> s32 (same fragment byte-layout as bf16 m16n8k16)
#define MMAI(D,a0,a1,a2,a3,b0,b1) \
    asm volatile("mma.sync.aligned.m16n8k32.row.col.s32.s8.s8.s32 " \
        "{%0,%1,%2,%3},{%4,%5,%6,%7},{%8,%9},{%0,%1,%2,%3};" \
        : "+r"((D)[0]), "+r"((D)[1]), "+r"((D)[2]), "+r"((D)[3]) \
        : "r"(a0), "r"(a1), "r"(a2), "r"(a3), "r"(b0), "r"(b1))

__device__ __forceinline__ void cp16(uint32_t dst, const void* src) {
    asm volatile("cp.async.cg.shared.global [%0], [%1], 16;"
                 :: "r"(dst), "l"(src) : "memory");
}
#define CP_COMMIT() asm volatile("cp.async.commit_group;" ::: "memory")
#define CP_WAIT1()  asm volatile("cp.async.wait_group 1;" ::: "memory")

// ---------------- 1. normalize patch -> fp32 + int8 (+ init pads) --------
__global__ void k_prep_patch(const float* __restrict__ patch) {
    int n = blockIdx.x, t = threadIdx.x;  // 128 thr
    if (n >= N_PATCH) {
        #pragma unroll
        for (int j = 0; j < 3; j++) g_patch_i8[n * DIM + t + 128 * j] = 0;
        int idx = (n - N_PATCH) * 128 + t;
        if (idx < NPAD) g_minbuf[idx] = ~0ull;
        return;
    }
    __shared__ float red[128];
    float v[3]; float ss = 0.f;
    #pragma unroll
    for (int j = 0; j < 3; j++) { v[j] = patch[(size_t)n * DIM + t + 128 * j]; ss += v[j] * v[j]; }
    red[t] = ss; __syncthreads();
    for (int s = 64; s > 0; s >>= 1) { if (t < s) red[t] += red[t + s]; __syncthreads(); }
    float denom = fmaxf(sqrtf(red[0]), 1e-12f);
    __syncthreads();
    float x[3]; float pn = 0.f, amax = 0.f;
    #pragma unroll
    for (int j = 0; j < 3; j++) {
        x[j] = v[j] / denom; pn += x[j] * x[j];
        amax = fmaxf(amax, fabsf(x[j]));
        g_patch_n[n * DIM + t + 128 * j] = x[j];
    }
    red[t] = pn; __syncthreads();
    for (int s = 64; s > 0; s >>= 1) { if (t < s) red[t] += red[t + s]; __syncthreads(); }
    if (t == 0) g_pn[n] = red[0];
    __syncthreads();
    red[t] = amax; __syncthreads();
    for (int s = 64; s > 0; s >>= 1) { if (t < s) red[t] = fmaxf(red[t], red[t + s]); __syncthreads(); }
    float qs = 127.f / fmaxf(red[0], 1e-12f);
    #pragma unroll
    for (int j = 0; j < 3; j++)
        g_patch_i8[n * DIM + t + 128 * j] = (signed char)__float2int_rn(x[j] * qs);
}

// ---------------- 2. lib fp32 -> int8 + per-row scale ---------------------
__global__ void k_prep_lib(const float* __restrict__ lib) {
    int w = threadIdx.x >> 5, lane = threadIdx.x & 31;
    int row = blockIdx.x * 8 + w;
    const float4* src = (const float4*)(lib + (size_t)row * DIM);
    float4 f[3]; float amax = 0.f;
    #pragma unroll
    for (int j = 0; j < 3; j++) {
        f[j] = src[lane + 32 * j];
        amax = fmaxf(amax, fmaxf(fmaxf(fabsf(f[j].x), fabsf(f[j].y)),
                                 fmaxf(fabsf(f[j].z), fabsf(f[j].w))));
    }
    #pragma unroll
    for (int o = 16; o; o >>= 1) amax = fmaxf(amax, __shfl_xor_sync(0xffffffffu, amax, o));
    float qs = 127.f / fmaxf(amax, 1e-12f);
    unsigned* dst = (unsigned*)(g_lib_i8 + (size_t)row * DIM);
    #pragma unroll
    for (int j = 0; j < 3; j++) {
        int q0 = __float2int_rn(f[j].x * qs) & 255;
        int q1 = __float2int_rn(f[j].y * qs) & 255;
        int q2 = __float2int_rn(f[j].z * qs) & 255;
        int q3 = __float2int_rn(f[j].w * qs) & 255;
        dst[lane + 32 * j] = (unsigned)(q0 | (q1 << 8) | (q2 << 16) | (q3 << 24));
    }
    if (lane == 0) g_lscale[row] = amax * (1.f / 127.f);
}

// ---------------- 4. fused int8 IMMA GEMM + per-patch-row max (ls*dot) ----
// grid 296 = 8 n-chunks x 37 stripes; 256 threads; TWO CTAs per SM.
// CTA tile 128m x 96n, 8 warps as 4 wm x 2 wn, warp tile 32m x 48n.
// Lib streamed as 128-row tiles in 3 k-thirds (128 int8, 128B pitch).
__global__ void __launch_bounds__(256, 2) k_main() {
    extern __shared__ char sm[];
    const uint32_t smb = smem_u32(sm);
    unsigned long long* sMin = (unsigned long long*)(sm + SM_MIN);
    const int tid = threadIdx.x;
    const int warp = tid >> 5, lane = tid & 31;
    const int nc = blockIdx.x & 7;
    const int mBase = (blockIdx.x >> 3) * STRIPE;

    if (tid < 96) sMin[tid] = ~0ull;

    // --- stage resident patch chunk [96 x 384] int8, swizzled 384B rows ---
    for (int i = tid; i < 96 * 24; i += 256) {
        int r = i / 24, u = i % 24;
        uint32_t dst = smb + SM_P + r * 384 + (((u ^ (r & 7))) << 4);
        cp16(dst, g_patch_i8 + (size_t)(nc * 96 + r) * DIM + u * 16);
    }
    // --- prologue: stage0 (grouped with patch), stage1 ---
    const int pu = tid & 7, pr0 = tid >> 3;    // 4 rows per thread
    #pragma unroll
    for (int p = 0; p < 2; p++) {
        #pragma unroll
        for (int j = 0; j < 4; j++) {
            int r = pr0 + 32 * j;
            cp16(smb + SM_L + p * STG_BYTES + r * 128 + (((pu ^ (r & 7))) << 4),
                 g_lib_i8 + (size_t)(mBase + r) * DIM + p * 128 + pu * 16);
        }
        CP_COMMIT();
    }

    // --- per-thread invariants ---
    const int wm = warp & 3, wn = warp >> 2;      // 4 x 2, warp tile 32m x 48n
    const unsigned hiA = (lane >> 4);             // k 16B-half select
    const unsigned hiB = (lane >> 3) & 1;
    unsigned baseA[2], swA[2];
    #pragma unroll
    for (int mf = 0; mf < 2; mf++) {
        unsigned rA = 32 * wm + 16 * mf + (lane & 15);
        baseA[mf] = rA * 128;
        swA[mf] = rA & 7;
    }
    unsigned pBase[3], swB[3];
    #pragma unroll
    for (int f2 = 0; f2 < 3; f2++) {
        unsigned rB = 48 * wn + 16 * f2 + (lane & 7) + ((lane >> 4) << 3);
        pBase[f2] = smb + SM_P + rB * 384;
        swB[f2] = rB & 7;
    }
    const int g8 = lane >> 2, tig = lane & 3;

    float runV[12]; int runI[12];
    #pragma unroll
    for (int j = 0; j < 12; j++) { runV[j] = -INF_F; runI[j] = 0; }

    int acc[12][4];
    #pragma unroll
    for (int g = 0; g < 12; g++) acc[g][0] = acc[g][1] = acc[g][2] = acc[g][3] = 0;

    int s = 0, q = 0, tile = 0;
    for (int i = 0; i < NITER; i++) {
        CP_WAIT1();
        __syncthreads();
        // compute stage i: 4 ksteps of k32, 2 A-frags + 3 B-LDSM (6 n8-frags)
        const unsigned stgA = smb + SM_L + s * STG_BYTES;
        const unsigned pq = q * 8;                // unit offset within 384B patch row
        #pragma unroll
        for (int ks = 0; ks < 4; ks++) {
            unsigned a[2][4];
            unsigned uA = 2 * ks + hiA;
            #pragma unroll
            for (int mf = 0; mf < 2; mf++)
                LDSM4(a[mf][0], a[mf][1], a[mf][2], a[mf][3],
                      stgA + baseA[mf] + (((uA ^ swA[mf])) << 4));
            unsigned uB = pq + hiB + 2 * ks;
            #pragma unroll
            for (int f2 = 0; f2 < 3; f2++) {
                unsigned r0, r1, r2, r3;
                LDSM4(r0, r1, r2, r3, pBase[f2] + (((uB ^ swB[f2])) << 4));
                #pragma unroll
                for (int mf = 0; mf < 2; mf++) {
                    MMAI(acc[(mf * 3 + f2) * 2],     a[mf][0], a[mf][1], a[mf][2], a[mf][3], r0, r1);
                    MMAI(acc[(mf * 3 + f2) * 2 + 1], a[mf][0], a[mf][1], a[mf][2], a[mf][3], r2, r3);
                }
            }
        }
        __syncthreads();
        // prefetch stage i+2 into the buffer just consumed
        {
            int nx = i + 2;
            if (nx < NITER) {
                int tN = nx / 3, qN = nx - tN * 3;
                const signed char* srcb = g_lib_i8 + (size_t)qN * 128
                                        + (size_t)(mBase + tN * 128) * DIM + pu * 16;
                #pragma unroll
                for (int j = 0; j < 4; j++) {
                    int r = pr0 + 32 * j;
                    cp16(smb + SM_L + s * STG_BYTES + r * 128 + (((pu ^ (r & 7))) << 4),
                         srcb + (size_t)r * DIM);
                }
            }
            CP_COMMIT();
        }
        s ^= 1;
        q++;
        if (q == 3) {
            q = 0;
            // tile epilogue: dequant by lib row scale, fold into running max
            int mt = mBase + tile * 128;
            #pragma unroll
            for (int mf = 0; mf < 2; mf++) {
                int mlo = mt + 32 * wm + 16 * mf + g8, mhi = mlo + 8;
                float lsLo = __ldg(&g_lscale[mlo]), lsHi = __ldg(&g_lscale[mhi]);
                #pragma unroll
                for (int f2 = 0; f2 < 3; f2++) {
                    int g = (mf * 3 + f2) * 2;
                    int jj = (g % 6) * 2;
                    #pragma unroll
                    for (int nh = 0; nh < 2; nh++) {
                        #pragma unroll
                        for (int c = 0; c < 2; c++) {
                            float vlo = lsLo * (float)acc[g + nh][c];
                            float vhi = lsHi * (float)acc[g + nh][2 + c];
                            int col = jj + nh * 2 + c - (g % 6) * 2 + (g % 6) * 2; // = jj+2nh+c
                            int j2 = (g % 6) * 2 + 0; (void)j2; (void)col;
                            int jx = ((g + nh) % 6) * 2 + c;
                            if (vlo > runV[jx]) { runV[jx] = vlo; runI[jx] = mlo; }
                            if (vhi > runV[jx]) { runV[jx] = vhi; runI[jx] = mhi; }
                        }
                        acc[g + nh][0] = acc[g + nh][1] = acc[g + nh][2] = acc[g + nh][3] = 0;
                    }
                }
            }
            tile++;
        }
    }

    // reduce over the 8 lanes sharing each column
    #pragma unroll
    for (int off = 4; off < 32; off <<= 1) {
        #pragma unroll
        for (int j = 0; j < 12; j++) {
            float ov = __shfl_xor_sync(0xffffffffu, runV[j], off);
            int   oi = __shfl_xor_sync(0xffffffffu, runI[j], off);
            if (ov > runV[j]) { runV[j] = ov; runI[j] = oi; }
        }
    }
    if (g8 == 0) {
        #pragma unroll
        for (int jj = 0; jj < 12; jj++) {
            int f2 = jj >> 2, nh = (jj >> 1) & 1, c = jj & 1;
            int col = 48 * wn + 16 * f2 + 8 * nh + 2 * tig + c;
            atomicMin(&sMin[col], packkey(-runV[jj], runI[jj]));
        }
    }
    __syncthreads();
    if (tid < 96) atomicMin(&g_minbuf[nc * 96 + tid], sMin[tid]);
}

// ---------------- 4b. exact fp32 rescore of each row's argmin -------------
__global__ void k_rescore(const float* __restrict__ lib) {
    int w = threadIdx.x >> 5, lane = threadIdx.x & 31;
    int n = blockIdx.x * 8 + w;
    if (n >= N_PATCH) return;
    int mi = (int)(g_minbuf[n] & 0xffffffffu);
    const float* a = g_patch_n + n * DIM;
    const float* b = lib + (size_t)mi * DIM;
    float dot = 0.f, bn = 0.f;
    #pragma unroll
    for (int j = 0; j < 12; j++) {
        float av = a[lane + 32 * j], bv = b[lane + 32 * j];
        dot = fmaf(av, bv, dot); bn = fmaf(bv, bv, bn);
    }
    #pragma unroll
    for (int o = 16; o; o >>= 1) {
        dot += __shfl_xor_sync(0xffffffffu, dot, o);
        bn  += __shfl_xor_sync(0xffffffffu, bn, o);
    }
    if (lane == 0)
        g_minval[n] = sqrtf(fmaxf(g_pn[n] + bn - 2.f * dot, 0.f));
}

// ---------------- 5. argmax over n ----------------------------------------
__global__ void k_nmin() {
    int t = threadIdx.x;  // 704 = 22 warps
    int lane = t & 31, w = t >> 5;
    __shared__ float sv[22]; __shared__ int si[22];
    float mv = (t < N_PATCH) ? g_minval[t] : -INF_F;
    int idx = (t < N_PATCH) ? t : 0;
    #pragma unroll
    for (int o = 16; o; o >>= 1) {
        float ov = __shfl_xor_sync(0xffffffffu, mv, o);
        int oi = __shfl_xor_sync(0xffffffffu, idx, o);
        if (ov > mv) { mv = ov; idx = oi; }
    }
    if (lane == 0) { sv[w] = mv; si[w] = idx; }
    __syncthreads();
    if (t < 32) {
        mv = (t < 22) ? sv[t] : -INF_F;
        idx = (t < 22) ? si[t] : 0;
        #pragma unroll
        for (int o = 16; o; o >>= 1) {
            float ov = __shfl_xor_sync(0xffffffffu, mv, o);
            int oi = __shfl_xor_sync(0xffffffffu, idx, o);
            if (ov > mv) { mv = ov; idx = oi; }
        }
        if (t == 0) {
            g_sidx = idx; g_sstar = mv;
            g_mstar_idx = (int)(g_minbuf[idx] & 0xffffffffu);
        }
    }
}

// ---------------- 6. int8 dot of every lib row vs m_star (ranking only) ---
__global__ void k_pass2() {
    int w = threadIdx.x >> 5, lane = threadIdx.x & 31;
    int row = blockIdx.x * 8 + w;
    int msi = g_mstar_idx;
    const int* a = (const int*)(g_lib_i8 + (size_t)row * DIM);
    const int* b = (const int*)(g_lib_i8 + (size_t)msi * DIM);
    int dot = 0;
    #pragma unroll
    for (int j = 0; j < 3; j++)
        dot = __dp4a(a[lane + 32 * j], b[lane + 32 * j], dot);
    #pragma unroll
    for (int o = 16; o; o >>= 1) dot += __shfl_xor_sync(0xffffffffu, dot, o);
    if (lane == 0) g_d2star[row] = -g_lscale[row] * (float)dot;
}

// ---------------- 7. top-5 smallest, block stage ----------------
__global__ void k_topscan() {
    unsigned long long best[5];
    #pragma unroll
    for (int r = 0; r < 5; r++) best[r] = ~0ull;
    for (int m = blockIdx.x * 256 + threadIdx.x; m < M_LIB; m += 64 * 256) {
        unsigned long long key = packkey(g_d2star[m], m);
        if (key < best[4]) {
            best[4] = key;
            #pragma unroll
            for (int r = 4; r > 0; r--)
                if (best[r] < best[r - 1]) { unsigned long long tm = best[r]; best[r] = best[r - 1]; best[r - 1] = tm; }
        }
    }
    __shared__ unsigned long long sb[5 * 256], red[256], winner;
    int t = threadIdx.x;
    #pragma unroll
    for (int r = 0; r < 5; r++) sb[r * 256 + t] = best[r];
    __syncthreads();
    for (int round = 0; round < 5; round++) {
        unsigned long long mn = ~0ull;
        #pragma unroll
        for (int r = 0; r < 5; r++) mn = ullmin2(mn, sb[r * 256 + t]);
        red[t] = mn; __syncthreads();
        for (int s = 128; s > 0; s >>= 1) { if (t < s) red[t] = ullmin2(red[t], red[t + s]); __syncthreads(); }
        if (t == 0) { winner = red[0]; g_btop[blockIdx.x * 5 + round] = red[0]; }
        __syncthreads();
        unsigned long long wv = winner;
        #pragma unroll
        for (int r = 0; r < 5; r++) if (sb[r * 256 + t] == wv) sb[r * 256 + t] = ~0ull;
        __syncthreads();
    }
}

// ---------------- 8. top-5 final merge ----------------
__global__ void k_topfinal() {
    __shared__ unsigned long long sb[320], red[256], winner;
    int t = threadIdx.x;  // 256
    sb[t] = g_btop[t];
    if (t < 64) sb[256 + t] = g_btop[256 + t];
    __syncthreads();
    for (int round = 0; round < 5; round++) {
        unsigned long long mn = sb[t];
        if (t < 64) mn = ullmin2(mn, sb[256 + t]);
        red[t] = mn; __syncthreads();
        for (int s = 128; s > 0; s >>= 1) { if (t < s) red[t] = ullmin2(red[t], red[t + s]); __syncthreads(); }
        if (t == 0) { winner = red[0]; g_nn[round] = (int)(red[0] & 0xffffffffu); }
        __syncthreads();
        unsigned long long wv = winner;
        if (sb[t] == wv) sb[t] = ~0ull;
        if (t < 64 && sb[256 + t] == wv) sb[256 + t] = ~0ull;
        __syncthreads();
    }
}

// ---------------- 9. scalar s (exact fp32) ----------------
__global__ void k_scalar(const float* __restrict__ lib, float* __restrict__ out, int write_s) {
    __shared__ float red[6][128];
    int t = threadIdx.x;  // 128
    int sidx = g_sidx, msi = g_mstar_idx;
    int nn[5];
    #pragma unroll
    for (int i = 0; i < 5; i++) nn[i] = g_nn[i];
    float ss[6] = {0.f, 0.f, 0.f, 0.f, 0.f, 0.f};
    #pragma unroll
    for (int j = 0; j < 3; j++) {
        int col = t + 128 * j;
        float p = g_patch_n[sidx * DIM + col];
        float d0 = p - lib[(size_t)msi * DIM + col];
        ss[0] += d0 * d0;
        #pragma unroll
        for (int i = 0; i < 5; i++) {
            float d = p - lib[(size_t)nn[i] * DIM + col];
            ss[1 + i] += d * d;
        }
    }
    #pragma unroll
    for (int q = 0; q < 6; q++) red[q][t] = ss[q];
    __syncthreads();
    for (int s = 64; s > 0; s >>= 1) {
        if (t < s) {
            #pragma unroll
            for (int q = 0; q < 6; q++) red[q][t] += red[q][t + s];
        }
        __syncthreads();
    }
    if (t == 0 && write_s) {
        float num = expf(sqrtf(red[0][0]));
        float den = 0.f;
        #pragma unroll
        for (int i = 0; i < 5; i++) den += expf(sqrtf(red[1 + i][0]));
        out[0] = (1.f - num / den) * g_sstar;
    }
}

// ---------------- 10. fused bilinear 26->224 + separable 33-tap blur ------
__device__ __forceinline__ int reflect_idx(int j) {
    if (j < 0) j = -j;
    if (j > IMG - 1) j = 2 * (IMG - 1) - j;
    return j;
}
__device__ __forceinline__ float upsample_val(int y, int x) {
    const float scale = 26.f / 224.f;
    float sx = (x + 0.5f) * scale - 0.5f;
    float sy = (y + 0.5f) * scale - 0.5f;
    int x0 = (int)floorf(sx), y0 = (int)floorf(sy);
    float fx = sx - x0, fy = sy - y0;
    int x0c = min(max(x0, 0), 25), x1c = min(max(x0 + 1, 0), 25);
    int y0c = min(max(y0, 0), 25), y1c = min(max(y0 + 1, 0), 25);
    float v00 = g_minval[y0c * 26 + x0c], v01 = g_minval[y0c * 26 + x1c];
    float v10 = g_minval[y1c * 26 + x0c], v11 = g_minval[y1c * 26 + x1c];
    float top = v00 + fx * (v01 - v00), bot = v10 + fx * (v11 - v10);
    return top + fy * (bot - top);
}
__global__ void k_map(float* __restrict__ out) {
    __shared__ float band[40][IMG];
    __shared__ float bv[8][IMG];
    int b = blockIdx.x, t = threadIdx.x;  // 28 blocks x 256 thr
    int y0 = b * 8;
    float w[33];
    {
        float s = 0.f;
        #pragma unroll
        for (int i = 0; i < 33; i++) {
            float xx = (float)(i - KRAD) / SIGMA;
            w[i] = expf(-0.5f * xx * xx); s += w[i];
        }
        float inv = 1.f / s;
        #pragma unroll
        for (int i = 0; i < 33; i++) w[i] *= inv;
    }
    for (int i = t; i < 40 * IMG; i += 256) {
        int k = i / IMG, x = i % IMG;
        band[k][x] = upsample_val(reflect_idx(y0 - KRAD + k), x);
    }
    __syncthreads();
    for (int i = t; i < 8 * IMG; i += 256) {
        int yy = i / IMG, x = i % IMG;
        float acc = 0.f;
        #pragma unroll
        for (int j = 0; j < 33; j++) acc += w[j] * band[yy + j][x];
        bv[yy][x] = acc;
    }
    __syncthreads();
    for (int i = t; i < 8 * IMG; i += 256) {
        int yy = i / IMG, x = i % IMG;
        float acc = 0.f;
        #pragma unroll
        for (int j = 0; j < 33; j++) acc += w[j] * bv[yy][reflect_idx(x + j - KRAD)];
        out[(y0 + yy) * IMG + x] = acc;
    }
}

extern "C" void kernel_launch(void* const* d_in, const int* in_sizes, int n_in,
                              void* d_out, int out_size) {
    const float* patch = (const float*)d_in[0];
    const float* lib   = (const float*)d_in[1];
    if (n_in >= 2 && in_sizes[0] != N_PATCH * DIM) {
        patch = (const float*)d_in[1]; lib = (const float*)d_in[0];
    }
    float* out = (float*)d_out;
    int ofs = out_size - IMG * IMG;
    if (ofs < 0) ofs = 0;

    static int smem_set = 0;
    if (!smem_set) {
        cudaFuncSetAttribute(k_main, cudaFuncAttributeMaxDynamicSharedMemorySize, SMEM_MAIN);
        smem_set = 1;
    }

    k_prep_patch<<<NPAD, 128>>>(patch);
    k_prep_lib<<<M_LIB / 8, 256>>>(lib);
    k_main<<<296, 256, SMEM_MAIN>>>();
    k_rescore<<<85, 256>>>(lib);
    k_nmin<<<1, 704>>>();
    k_pass2<<<M_LIB / 8, 256>>>();
    k_topscan<<<64, 256>>>();
    k_topfinal<<<1, 256>>>();
    k_scalar<<<1, 128>>>(lib, out, ofs > 0 ? 1 : 0);
    k_map<<<28, 256>>>(out + ofs);
}

// round 17
// speedup vs baseline: 1.4660x; 1.4660x over previous
#include <cuda_runtime.h>
#include <cuda_bf16.h>
#include <math.h>
#include <stdint.h>

#define M_LIB   200000
#define M_PAD   203648          // 37 * 5504, zero-padded tail (bss)
#define N_PATCH 676
#define NPAD    768
#define DIM     384
#define IMG     224
#define SIGMA   4.0f
#define KRAD    16

#define NTILES  43              // 128-row tiles per stripe; 37 stripes
#define STRIPE  (128*NTILES)    // 5504
#define NITER   (NTILES*6)      // 258 k-sixth stages
#define STG_BYTES (128*128)     // one stage: 128 rows x 64 k-elems bf16 (128B pitch)
#define SM_P    0               // patch chunk 96 x 768B = 73728
#define SM_L    73728
#define SM_MIN  (SM_L + 2*STG_BYTES)   // 106496
#define SMEM_MAIN (SM_MIN + 96*8)      // 107264

// ---------------- device scratch ----------------
__device__ __align__(16) __nv_bfloat16 g_lib_bf16[(size_t)M_PAD * DIM];  // pad rows stay 0
__device__ float g_patch_n[N_PATCH * DIM];
__device__ __align__(16) __nv_bfloat16 g_patch_bf16[NPAD * DIM];
__device__ float g_pn[N_PATCH];
__device__ unsigned long long g_minbuf[NPAD];
__device__ float g_minval[N_PATCH];
__device__ int   g_sidx;
__device__ int   g_mstar_idx;
__device__ float g_sstar;
__device__ unsigned long long g_btop[64 * 5];

// ---------------- helpers ----------------
__device__ __forceinline__ unsigned fordu(float f) {
    unsigned u = __float_as_uint(f);
    return (u & 0x80000000u) ? ~u : (u | 0x80000000u);
}
__device__ __forceinline__ float fordu_inv(unsigned e) {
    return __uint_as_float((e & 0x80000000u) ? (e ^ 0x80000000u) : ~e);
}
__device__ __forceinline__ unsigned long long packkey(float v, int idx) {
    return ((unsigned long long)fordu(v) << 32) | (unsigned)idx;
}
__device__ __forceinline__ unsigned long long ullmin2(unsigned long long a, unsigned long long b) {
    return a < b ? a : b;
}
#define INF_F (__int_as_float(0x7f800000))

__device__ __forceinline__ uint32_t smem_u32(const void* p) {
    return (uint32_t)__cvta_generic_to_shared(p);
}

#define LDSM4(r0,r1,r2,r3,addr) \
    asm volatile("ldmatrix.sync.aligned.m8n8.x4.shared.b16 {%0,%1,%2,%3}, [%4];" \
        : "=r"(r0), "=r"(r1), "=r"(r2), "=r"(r3) : "r"(addr))
#define MMA16816(D,a0,a1,a2,a3,b0,b1) \
    asm volatile("mma.sync.aligned.m16n8k16.row.col.f32.bf16.bf16.f32 " \
        "{%0,%1,%2,%3},{%4,%5,%6,%7},{%8,%9},{%0,%1,%2,%3};" \
        : "+f"((D)[0]), "+f"((D)[1]), "+f"((D)[2]), "+f"((D)[3]) \
        : "r"(a0), "r"(a1), "r"(a2), "r"(a3), "r"(b0), "r"(b1))

__device__ __forceinline__ void cp16(uint32_t dst, const void* src) {
    asm volatile("cp.async.cg.shared.global [%0], [%1], 16;"
                 :: "r"(dst), "l"(src) : "memory");
}
#define CP_COMMIT() asm volatile("cp.async.commit_group;" ::: "memory")
#define CP_WAIT1()  asm volatile("cp.async.wait_group 1;" ::: "memory")

// ---------------- 1. normalize patch (+ minbuf init in padding blocks) ----
__global__ void k_prep_patch(const float* __restrict__ patch) {
    int n = blockIdx.x, t = threadIdx.x;  // 128 thr
    if (n >= N_PATCH) {
        #pragma unroll
        for (int j = 0; j < 3; j++) g_patch_bf16[n * DIM + t + 128 * j] = __float2bfloat16(0.f);
        int idx = (n - N_PATCH) * 128 + t;
        if (idx < NPAD) g_minbuf[idx] = ~0ull;
        return;
    }
    __shared__ float red[128];
    float v[3]; float ss = 0.f;
    #pragma unroll
    for (int j = 0; j < 3; j++) { v[j] = patch[(size_t)n * DIM + t + 128 * j]; ss += v[j] * v[j]; }
    red[t] = ss; __syncthreads();
    for (int s = 64; s > 0; s >>= 1) { if (t < s) red[t] += red[t + s]; __syncthreads(); }
    float denom = fmaxf(sqrtf(red[0]), 1e-12f);
    __syncthreads();
    float pn = 0.f;
    #pragma unroll
    for (int j = 0; j < 3; j++) {
        float x = v[j] / denom; pn += x * x;
        g_patch_n[n * DIM + t + 128 * j] = x;
        g_patch_bf16[n * DIM + t + 128 * j] = __float2bfloat16(x);
    }
    red[t] = pn; __syncthreads();
    for (int s = 64; s > 0; s >>= 1) { if (t < s) red[t] += red[t + s]; __syncthreads(); }
    if (t == 0) g_pn[n] = red[0];
}

// ---------------- 2. lib fp32 -> bf16 (pure convert; lib is pre-normalized) -
__global__ void k_prep_lib(const float* __restrict__ lib) {
    int w = threadIdx.x >> 5, lane = threadIdx.x & 31;
    int row = blockIdx.x * 8 + w;
    const float4* src = (const float4*)(lib + (size_t)row * DIM);
    __nv_bfloat162* dst = (__nv_bfloat162*)(g_lib_bf16 + (size_t)row * DIM);
    #pragma unroll
    for (int j = 0; j < 3; j++) {
        float4 f = src[lane + 32 * j];
        dst[2 * (lane + 32 * j)]     = __floats2bfloat162_rn(f.x, f.y);
        dst[2 * (lane + 32 * j) + 1] = __floats2bfloat162_rn(f.z, f.w);
    }
}

// ---------------- 4. fused bf16 HMMA GEMM + per-patch-row max-dot ----------
// grid 296 = 8 n-chunks x 37 stripes; 256 threads; TWO CTAs per SM.
// CTA tile 128m x 96n, 8 warps as 4 wm x 2 wn, warp tile 32m x 48n.
// Lib zero-padded to M_PAD: no bounds checks anywhere in the hot loop.
__global__ void __launch_bounds__(256, 2) k_main() {
    extern __shared__ char sm[];
    const uint32_t smb = smem_u32(sm);
    unsigned long long* sMin = (unsigned long long*)(sm + SM_MIN);
    const int tid = threadIdx.x;
    const int warp = tid >> 5, lane = tid & 31;
    const int nc = blockIdx.x & 7;
    const int mBase = (blockIdx.x >> 3) * STRIPE;

    if (tid < 96) sMin[tid] = ~0ull;

    // --- stage resident patch chunk [96 x 384] bf16, swizzled 768B rows ---
    for (int i = tid; i < 96 * 48; i += 256) {
        int r = i / 48, u = i % 48;
        uint32_t dst = smb + SM_P + r * 768 + (((u ^ (r & 7))) << 4);
        cp16(dst, g_patch_bf16 + (size_t)(nc * 96 + r) * DIM + u * 8);
    }
    // --- prologue: stage0 (grouped with patch), stage1 ---
    const int pu = tid & 7, pr0 = tid >> 3;    // 4 rows per thread
    #pragma unroll
    for (int p = 0; p < 2; p++) {
        #pragma unroll
        for (int j = 0; j < 4; j++) {
            int r = pr0 + 32 * j;
            cp16(smb + SM_L + p * STG_BYTES + r * 128 + (((pu ^ (r & 7))) << 4),
                 g_lib_bf16 + (size_t)(mBase + r) * DIM + p * 64 + pu * 8);
        }
        CP_COMMIT();
    }

    // --- per-thread invariants ---
    const int wm = warp & 3, wn = warp >> 2;      // 4 x 2, warp tile 32m x 48n
    const unsigned hiA = (lane >> 4);
    const unsigned hiB = (lane >> 3) & 1;
    unsigned baseA[2], swA[2];
    #pragma unroll
    for (int mf = 0; mf < 2; mf++) {
        unsigned rA = 32 * wm + 16 * mf + (lane & 15);
        baseA[mf] = rA * 128;
        swA[mf] = rA & 7;
    }
    unsigned pBase[3], swB[3];
    #pragma unroll
    for (int f2 = 0; f2 < 3; f2++) {
        unsigned rB = 48 * wn + 16 * f2 + (lane & 7) + ((lane >> 4) << 3);
        pBase[f2] = smb + SM_P + rB * 768;
        swB[f2] = rB & 7;
    }
    const int g8 = lane >> 2, tig = lane & 3;

    float runV[12]; int runI[12];
    #pragma unroll
    for (int j = 0; j < 12; j++) { runV[j] = -INF_F; runI[j] = 0; }

    float acc[12][4];
    #pragma unroll
    for (int g = 0; g < 12; g++) acc[g][0] = acc[g][1] = acc[g][2] = acc[g][3] = 0.f;

    int s = 0, q = 0, tile = 0;
    for (int i = 0; i < NITER; i++) {
        CP_WAIT1();
        __syncthreads();
        // compute stage i: 4 ksteps, 2 A-frags + 3 B-frags, 12 MMAs each
        const unsigned stgA = smb + SM_L + s * STG_BYTES;
        const unsigned pq = q * 128;
        #pragma unroll
        for (int ks = 0; ks < 4; ks++) {
            unsigned a[2][4];
            unsigned uA = 2 * ks + hiA;
            #pragma unroll
            for (int mf = 0; mf < 2; mf++)
                LDSM4(a[mf][0], a[mf][1], a[mf][2], a[mf][3],
                      stgA + baseA[mf] + (((uA ^ swA[mf])) << 4));
            unsigned uB = hiB + 2 * ks;
            #pragma unroll
            for (int f2 = 0; f2 < 3; f2++) {
                unsigned r0, r1, r2, r3;
                LDSM4(r0, r1, r2, r3, pBase[f2] + pq + (((uB ^ swB[f2])) << 4));
                #pragma unroll
                for (int mf = 0; mf < 2; mf++) {
                    MMA16816(acc[(mf * 3 + f2) * 2],     a[mf][0], a[mf][1], a[mf][2], a[mf][3], r0, r1);
                    MMA16816(acc[(mf * 3 + f2) * 2 + 1], a[mf][0], a[mf][1], a[mf][2], a[mf][3], r2, r3);
                }
            }
        }
        __syncthreads();
        // prefetch stage i+2 into the buffer just consumed
        {
            int nx = i + 2;
            if (nx < NITER) {
                int tN = nx / 6, qN = nx - tN * 6;
                const __nv_bfloat16* srcb = g_lib_bf16 + (size_t)qN * 64
                                          + (size_t)(mBase + tN * 128) * DIM + pu * 8;
                #pragma unroll
                for (int j = 0; j < 4; j++) {
                    int r = pr0 + 32 * j;
                    cp16(smb + SM_L + s * STG_BYTES + r * 128 + (((pu ^ (r & 7))) << 4),
                         srcb + (size_t)r * DIM);
                }
            }
            CP_COMMIT();
        }
        s ^= 1;
        q++;
        if (q == 6) {
            q = 0;
            // tile epilogue: fold 128-row tile into per-column running max dot
            int mt = mBase + tile * 128;
            #pragma unroll
            for (int g = 0; g < 12; g++) {
                int mf = g / 6;
                int mlo = mt + 32 * wm + 16 * mf + g8, mhi = mlo + 8;
                int jj = (g % 6) * 2;
                #pragma unroll
                for (int c = 0; c < 2; c++) {
                    float vlo = acc[g][c], vhi = acc[g][2 + c];
                    if (vlo > runV[jj + c]) { runV[jj + c] = vlo; runI[jj + c] = mlo; }
                    if (vhi > runV[jj + c]) { runV[jj + c] = vhi; runI[jj + c] = mhi; }
                }
                acc[g][0] = acc[g][1] = acc[g][2] = acc[g][3] = 0.f;
            }
            tile++;
        }
    }

    // reduce over the 8 lanes sharing each column
    #pragma unroll
    for (int off = 4; off < 32; off <<= 1) {
        #pragma unroll
        for (int j = 0; j < 12; j++) {
            float ov = __shfl_xor_sync(0xffffffffu, runV[j], off);
            int   oi = __shfl_xor_sync(0xffffffffu, runI[j], off);
            if (ov > runV[j]) { runV[j] = ov; runI[j] = oi; }
        }
    }
    if (g8 == 0) {
        #pragma unroll
        for (int jj = 0; jj < 12; jj++) {
            int f2 = jj >> 2, nh = (jj >> 1) & 1, c = jj & 1;
            int col = 48 * wn + 16 * f2 + 8 * nh + 2 * tig + c;
            atomicMin(&sMin[col], packkey(-runV[jj], runI[jj]));
        }
    }
    __syncthreads();
    if (tid < 96) atomicMin(&g_minbuf[nc * 96 + tid], sMin[tid]);
}

// ---------------- 5. min_val per n + argmax over n (ln == 1) --------------
__global__ void k_nmin() {
    int t = threadIdx.x;  // 704 = 22 warps
    int lane = t & 31, w = t >> 5;
    __shared__ float sv[22]; __shared__ int si[22];
    float mv = -INF_F; int idx = 0;
    if (t < N_PATCH) {
        unsigned long long key = g_minbuf[t];
        float v = fordu_inv((unsigned)(key >> 32));   // = -max_dot
        float d2 = g_pn[t] + 1.0f + 2.f * v;
        mv = sqrtf(fmaxf(d2, 0.f));
        g_minval[t] = mv; idx = t;
    }
    #pragma unroll
    for (int o = 16; o; o >>= 1) {
        float ov = __shfl_xor_sync(0xffffffffu, mv, o);
        int oi = __shfl_xor_sync(0xffffffffu, idx, o);
        if (ov > mv) { mv = ov; idx = oi; }
    }
    if (lane == 0) { sv[w] = mv; si[w] = idx; }
    __syncthreads();
    if (t < 32) {
        mv = (t < 22) ? sv[t] : -INF_F;
        idx = (t < 22) ? si[t] : 0;
        #pragma unroll
        for (int o = 16; o; o >>= 1) {
            float ov = __shfl_xor_sync(0xffffffffu, mv, o);
            int oi = __shfl_xor_sync(0xffffffffu, idx, o);
            if (ov > mv) { mv = ov; idx = oi; }
        }
        if (t == 0) {
            g_sidx = idx; g_sstar = mv;
            g_mstar_idx = (int)(g_minbuf[idx] & 0xffffffffu);
        }
    }
}

// ---------------- 6+7 fused: -dot vs m_star + per-block top-5 -------------
__global__ void k_p2top() {
    int t = threadIdx.x, w = t >> 5, lane = t & 31;  // 64 blocks x 256 thr
    int msi = g_mstar_idx;
    const unsigned* bptr = (const unsigned*)(g_lib_bf16 + (size_t)msi * DIM);
    float2 fb[6];
    #pragma unroll
    for (int j = 0; j < 6; j++) {
        unsigned ub = bptr[lane + 32 * j];
        fb[j] = __bfloat1622float2(*(__nv_bfloat162*)&ub);
    }
    unsigned long long best[5];
    #pragma unroll
    for (int r = 0; r < 5; r++) best[r] = ~0ull;
    for (int row = blockIdx.x * 8 + w; row < M_LIB; row += 512) {
        const unsigned* a = (const unsigned*)(g_lib_bf16 + (size_t)row * DIM);
        float dot = 0.f;
        #pragma unroll
        for (int j = 0; j < 6; j++) {
            unsigned ua = a[lane + 32 * j];
            float2 fa = __bfloat1622float2(*(__nv_bfloat162*)&ua);
            dot = fmaf(fa.x, fb[j].x, dot); dot = fmaf(fa.y, fb[j].y, dot);
        }
        #pragma unroll
        for (int o = 16; o; o >>= 1) dot += __shfl_xor_sync(0xffffffffu, dot, o);
        if (lane == 0) {
            unsigned long long key = packkey(-dot, row);
            if (key < best[4]) {
                best[4] = key;
                #pragma unroll
                for (int r = 4; r > 0; r--)
                    if (best[r] < best[r - 1]) { unsigned long long tm = best[r]; best[r] = best[r - 1]; best[r - 1] = tm; }
            }
        }
    }
    __shared__ unsigned long long sb[40];
    if (lane == 0) {
        #pragma unroll
        for (int r = 0; r < 5; r++) sb[w * 5 + r] = best[r];
    }
    __syncthreads();
    if (t == 0) {
        #pragma unroll 1
        for (int round = 0; round < 5; round++) {
            unsigned long long mn = ~0ull; int mi = 0;
            for (int k = 0; k < 40; k++)
                if (sb[k] < mn) { mn = sb[k]; mi = k; }
            sb[mi] = ~0ull;
            g_btop[blockIdx.x * 5 + round] = mn;
        }
    }
}

// ---------------- 8+9 fused: top-5 final merge + scalar s -----------------
__global__ void k_final(const float* __restrict__ lib, float* __restrict__ out, int write_s) {
    __shared__ unsigned long long sb[320], red[256], winner;
    __shared__ int nn_s[5];
    __shared__ float red2[6][128];
    int t = threadIdx.x;  // 256
    sb[t] = g_btop[t];
    if (t < 64) sb[256 + t] = g_btop[256 + t];
    __syncthreads();
    for (int round = 0; round < 5; round++) {
        unsigned long long mn = sb[t];
        if (t < 64) mn = ullmin2(mn, sb[256 + t]);
        red[t] = mn; __syncthreads();
        for (int s = 128; s > 0; s >>= 1) { if (t < s) red[t] = ullmin2(red[t], red[t + s]); __syncthreads(); }
        if (t == 0) { winner = red[0]; nn_s[round] = (int)(red[0] & 0xffffffffu); }
        __syncthreads();
        unsigned long long wv = winner;
        if (sb[t] == wv) sb[t] = ~0ull;
        if (t < 64 && sb[256 + t] == wv) sb[256 + t] = ~0ull;
        __syncthreads();
    }
    // scalar phase (exact fp32)
    if (t < 128) {
        int sidx = g_sidx, msi = g_mstar_idx;
        int nn[5];
        #pragma unroll
        for (int i = 0; i < 5; i++) nn[i] = nn_s[i];
        float ss[6] = {0.f, 0.f, 0.f, 0.f, 0.f, 0.f};
        #pragma unroll
        for (int j = 0; j < 3; j++) {
            int col = t + 128 * j;
            float p = g_patch_n[sidx * DIM + col];
            float d0 = p - lib[(size_t)msi * DIM + col];
            ss[0] += d0 * d0;
            #pragma unroll
            for (int i = 0; i < 5; i++) {
                float d = p - lib[(size_t)nn[i] * DIM + col];
                ss[1 + i] += d * d;
            }
        }
        #pragma unroll
        for (int q = 0; q < 6; q++) red2[q][t] = ss[q];
    }
    __syncthreads();
    for (int s = 64; s > 0; s >>= 1) {
        if (t < s) {
            #pragma unroll
            for (int q = 0; q < 6; q++) red2[q][t] += red2[q][t + s];
        }
        __syncthreads();
    }
    if (t == 0 && write_s) {
        float num = expf(sqrtf(red2[0][0]));
        float den = 0.f;
        #pragma unroll
        for (int i = 0; i < 5; i++) den += expf(sqrtf(red2[1 + i][0]));
        out[0] = (1.f - num / den) * g_sstar;
    }
}

// ---------------- 10. fused bilinear 26->224 + separable 33-tap blur ------
__device__ __forceinline__ int reflect_idx(int j) {
    if (j < 0) j = -j;
    if (j > IMG - 1) j = 2 * (IMG - 1) - j;
    return j;
}
__device__ __forceinline__ float upsample_val(int y, int x) {
    const float scale = 26.f / 224.f;
    float sx = (x + 0.5f) * scale - 0.5f;
    float sy = (y + 0.5f) * scale - 0.5f;
    int x0 = (int)floorf(sx), y0 = (int)floorf(sy);
    float fx = sx - x0, fy = sy - y0;
    int x0c = min(max(x0, 0), 25), x1c = min(max(x0 + 1, 0), 25);
    int y0c = min(max(y0, 0), 25), y1c = min(max(y0 + 1, 0), 25);
    float v00 = g_minval[y0c * 26 + x0c], v01 = g_minval[y0c * 26 + x1c];
    float v10 = g_minval[y1c * 26 + x0c], v11 = g_minval[y1c * 26 + x1c];
    float top = v00 + fx * (v01 - v00), bot = v10 + fx * (v11 - v10);
    return top + fy * (bot - top);
}
__global__ void k_map(float* __restrict__ out) {
    __shared__ float band[40][IMG];
    __shared__ float bv[8][IMG];
    int b = blockIdx.x, t = threadIdx.x;  // 28 blocks x 256 thr
    int y0 = b * 8;
    float w[33];
    {
        float s = 0.f;
        #pragma unroll
        for (int i = 0; i < 33; i++) {
            float xx = (float)(i - KRAD) / SIGMA;
            w[i] = expf(-0.5f * xx * xx); s += w[i];
        }
        float inv = 1.f / s;
        #pragma unroll
        for (int i = 0; i < 33; i++) w[i] *= inv;
    }
    for (int i = t; i < 40 * IMG; i += 256) {
        int k = i / IMG, x = i % IMG;
        band[k][x] = upsample_val(reflect_idx(y0 - KRAD + k), x);
    }
    __syncthreads();
    for (int i = t; i < 8 * IMG; i += 256) {
        int yy = i / IMG, x = i % IMG;
        float acc = 0.f;
        #pragma unroll
        for (int j = 0; j < 33; j++) acc += w[j] * band[yy + j][x];
        bv[yy][x] = acc;
    }
    __syncthreads();
    for (int i = t; i < 8 * IMG; i += 256) {
        int yy = i / IMG, x = i % IMG;
        float acc = 0.f;
        #pragma unroll
        for (int j = 0; j < 33; j++) acc += w[j] * bv[yy][reflect_idx(x + j - KRAD)];
        out[(y0 + yy) * IMG + x] = acc;
    }
}

extern "C" void kernel_launch(void* const* d_in, const int* in_sizes, int n_in,
                              void* d_out, int out_size) {
    const float* patch = (const float*)d_in[0];
    const float* lib   = (const float*)d_in[1];
    if (n_in >= 2 && in_sizes[0] != N_PATCH * DIM) {
        patch = (const float*)d_in[1]; lib = (const float*)d_in[0];
    }
    float* out = (float*)d_out;
    int ofs = out_size - IMG * IMG;
    if (ofs < 0) ofs = 0;

    static int smem_set = 0;
    if (!smem_set) {
        cudaFuncSetAttribute(k_main, cudaFuncAttributeMaxDynamicSharedMemorySize, SMEM_MAIN);
        smem_set = 1;
    }

    k_prep_patch<<<NPAD, 128>>>(patch);
    k_prep_lib<<<M_LIB / 8, 256>>>(lib);
    k_main<<<296, 256, SMEM_MAIN>>>();
    k_nmin<<<1, 704>>>();
    k_p2top<<<64, 256>>>();
    k_final<<<1, 256>>>(lib, out, ofs > 0 ? 1 : 0);
    k_map<<<28, 256>>>(out + ofs);
}